// round 1
// baseline (speedup 1.0000x reference)
#include <cuda_runtime.h>
#include <math.h>

// ---------------------------------------------------------------------------
// ForegroundAttentionModule: B=4, C=512, T=2048, fp32
//
// Algebraic simplifications vs reference:
//  * key_ einsum 'oc,bct->bct' sums over o => k[b,c,t] = wksum[c]*feat + bk[c]
//  * z = (1-f)@v = colsum(v) - y  (softmax rows sum to 1)
// ---------------------------------------------------------------------------

namespace {

constexpr int B = 4;
constexpr int C = 512;
constexpr int T = 2048;
constexpr float LN_EPS = 1e-5f;
constexpr float INV_SQRT_C = 0.04419417382415922f;  // 1/sqrt(512)

// Scratch (device globals; no runtime allocation allowed)
__device__ float  g_q[(size_t)B * T * C];       // [B,T,C]
__device__ float  g_k[(size_t)B * C * T];       // [B,C,T]
__device__ float  g_v[(size_t)B * T * C];       // [B,T,C]
__device__ float  g_y[(size_t)B * T * C];       // [B,T,C]
__device__ float  g_f[(size_t)B * T * T];       // [B,T,T] attention (pre+post softmax)
__device__ float  g_vsum[B * C];                // colsum of v per batch
__device__ float  g_wksum[C];                   // sum_o Wk[o,c]
__device__ float  g_vsumWl[B];                  // dot(vsum[b], Wl)
__device__ double g_lnsum[B];
__device__ double g_lnsq[B];

__device__ __forceinline__ float sigmoidf_(float x) {
    return 1.0f / (1.0f + expf(-x));
}

// ---------------------------------------------------------------------------
// Zero per-call accumulators
// ---------------------------------------------------------------------------
__global__ void zero_kernel() {
    int i = threadIdx.x;
    if (i < B) { g_lnsum[i] = 0.0; g_lnsq[i] = 0.0; }
}

// ---------------------------------------------------------------------------
// wksum[c] = sum_o Wk[o,c]
// ---------------------------------------------------------------------------
__global__ void wksum_kernel(const float* __restrict__ Wk) {
    int c = blockIdx.x * 256 + threadIdx.x;
    if (c >= C) return;
    float s = 0.0f;
    for (int o = 0; o < C; ++o) s += Wk[(size_t)o * C + c];
    g_wksum[c] = s;
}

// ---------------------------------------------------------------------------
// k[b,c,t] = wksum[c]*feat[b,c,t] + bk[c]
// ---------------------------------------------------------------------------
__global__ void kscale_kernel(const float* __restrict__ feat,
                              const float* __restrict__ bk) {
    size_t i = (size_t)blockIdx.x * 256 + threadIdx.x;
    int c = (int)((i / T) % C);
    g_k[i] = g_wksum[c] * feat[i] + bk[c];
}

// ---------------------------------------------------------------------------
// Projection GEMM: out[b,t,o] = sum_c W[o,c]*feat[b,c,t] + bias[o]
// Tiles: 64(o) x 64(t) x 16(c). 256 threads, 4x4 per thread.
// ---------------------------------------------------------------------------
__global__ void proj_kernel(const float* __restrict__ W,
                            const float* __restrict__ bias,
                            const float* __restrict__ feat,
                            float* __restrict__ out) {
    __shared__ float As[16][64];  // [c][o]
    __shared__ float Bs[16][64];  // [c][t]
    const int b  = blockIdx.z;
    const int t0 = blockIdx.x * 64;
    const int o0 = blockIdx.y * 64;
    const int tid = threadIdx.x;
    const int tx = tid & 15, ty = tid >> 4;

    float acc[4][4] = {};
    for (int c0 = 0; c0 < C; c0 += 16) {
#pragma unroll
        for (int p = 0; p < 4; ++p) {
            int idx = p * 256 + tid;
            As[idx & 15][idx >> 4] = W[(size_t)(o0 + (idx >> 4)) * C + c0 + (idx & 15)];
            Bs[idx >> 6][idx & 63] = feat[((size_t)b * C + c0 + (idx >> 6)) * T + t0 + (idx & 63)];
        }
        __syncthreads();
#pragma unroll
        for (int kk = 0; kk < 16; ++kk) {
            float4 av = *reinterpret_cast<const float4*>(&As[kk][ty * 4]);
            float4 bv = *reinterpret_cast<const float4*>(&Bs[kk][tx * 4]);
            float a[4] = {av.x, av.y, av.z, av.w};
            float bb[4] = {bv.x, bv.y, bv.z, bv.w};
#pragma unroll
            for (int i = 0; i < 4; ++i)
#pragma unroll
                for (int j = 0; j < 4; ++j) acc[i][j] += a[i] * bb[j];
        }
        __syncthreads();
    }
#pragma unroll
    for (int i = 0; i < 4; ++i) {
        int o = o0 + ty * 4 + i;
        float bo = bias[o];
#pragma unroll
        for (int j = 0; j < 4; ++j) {
            int t = t0 + tx * 4 + j;
            out[((size_t)b * T + t) * C + o] = acc[i][j] + bo;
        }
    }
}

// ---------------------------------------------------------------------------
// QK^T: f[b,t,s] = (sum_c q[b,t,c]*k[b,c,s]) / sqrt(C)
// ---------------------------------------------------------------------------
__global__ void qk_kernel() {
    __shared__ float As[16][64];  // [c][t_row]
    __shared__ float Bs[16][64];  // [c][s]
    const int b  = blockIdx.z;
    const int s0 = blockIdx.x * 64;
    const int t0 = blockIdx.y * 64;
    const int tid = threadIdx.x;
    const int tx = tid & 15, ty = tid >> 4;

    float acc[4][4] = {};
    for (int c0 = 0; c0 < C; c0 += 16) {
#pragma unroll
        for (int p = 0; p < 4; ++p) {
            int idx = p * 256 + tid;
            As[idx & 15][idx >> 4] = g_q[((size_t)b * T + t0 + (idx >> 4)) * C + c0 + (idx & 15)];
            Bs[idx >> 6][idx & 63] = g_k[((size_t)b * C + c0 + (idx >> 6)) * T + s0 + (idx & 63)];
        }
        __syncthreads();
#pragma unroll
        for (int kk = 0; kk < 16; ++kk) {
            float4 av = *reinterpret_cast<const float4*>(&As[kk][ty * 4]);
            float4 bv = *reinterpret_cast<const float4*>(&Bs[kk][tx * 4]);
            float a[4] = {av.x, av.y, av.z, av.w};
            float bb[4] = {bv.x, bv.y, bv.z, bv.w};
#pragma unroll
            for (int i = 0; i < 4; ++i)
#pragma unroll
                for (int j = 0; j < 4; ++j) acc[i][j] += a[i] * bb[j];
        }
        __syncthreads();
    }
#pragma unroll
    for (int i = 0; i < 4; ++i) {
        int t = t0 + ty * 4 + i;
#pragma unroll
        for (int j = 0; j < 4; ++j) {
            int s = s0 + tx * 4 + j;
            g_f[((size_t)b * T + t) * T + s] = acc[i][j] * INV_SQRT_C;
        }
    }
}

// ---------------------------------------------------------------------------
// Row softmax over s (row length T=2048), in place on g_f
// ---------------------------------------------------------------------------
__global__ void softmax_kernel() {
    __shared__ float buf[T];
    __shared__ float red[256];
    const size_t base = (size_t)blockIdx.x * T;  // blockIdx.x = b*T + t
    const int tid = threadIdx.x;

    float m = -1e30f;
    for (int s = tid; s < T; s += 256) {
        float x = g_f[base + s];
        buf[s] = x;
        m = fmaxf(m, x);
    }
    red[tid] = m;
    __syncthreads();
    for (int off = 128; off > 0; off >>= 1) {
        if (tid < off) red[tid] = fmaxf(red[tid], red[tid + off]);
        __syncthreads();
    }
    m = red[0];
    __syncthreads();

    float sum = 0.0f;
    for (int s = tid; s < T; s += 256) {
        float e = expf(buf[s] - m);
        buf[s] = e;
        sum += e;
    }
    red[tid] = sum;
    __syncthreads();
    for (int off = 128; off > 0; off >>= 1) {
        if (tid < off) red[tid] += red[tid + off];
        __syncthreads();
    }
    float inv = 1.0f / red[0];
    for (int s = tid; s < T; s += 256) g_f[base + s] = buf[s] * inv;
}

// ---------------------------------------------------------------------------
// y[b,t,c] = sum_s f[b,t,s]*v[b,s,c]
// ---------------------------------------------------------------------------
__global__ void av_kernel() {
    __shared__ float As[16][64];  // [s][t_row]
    __shared__ float Bs[16][64];  // [s][c]
    const int b  = blockIdx.z;
    const int c0 = blockIdx.x * 64;
    const int t0 = blockIdx.y * 64;
    const int tid = threadIdx.x;
    const int tx = tid & 15, ty = tid >> 4;

    float acc[4][4] = {};
    for (int s0 = 0; s0 < T; s0 += 16) {
#pragma unroll
        for (int p = 0; p < 4; ++p) {
            int idx = p * 256 + tid;
            As[idx & 15][idx >> 4] = g_f[((size_t)b * T + t0 + (idx >> 4)) * T + s0 + (idx & 15)];
            Bs[idx >> 6][idx & 63] = g_v[((size_t)b * T + s0 + (idx >> 6)) * C + c0 + (idx & 63)];
        }
        __syncthreads();
#pragma unroll
        for (int kk = 0; kk < 16; ++kk) {
            float4 av = *reinterpret_cast<const float4*>(&As[kk][ty * 4]);
            float4 bv = *reinterpret_cast<const float4*>(&Bs[kk][tx * 4]);
            float a[4] = {av.x, av.y, av.z, av.w};
            float bb[4] = {bv.x, bv.y, bv.z, bv.w};
#pragma unroll
            for (int i = 0; i < 4; ++i)
#pragma unroll
                for (int j = 0; j < 4; ++j) acc[i][j] += a[i] * bb[j];
        }
        __syncthreads();
    }
#pragma unroll
    for (int i = 0; i < 4; ++i) {
        int t = t0 + ty * 4 + i;
#pragma unroll
        for (int j = 0; j < 4; ++j) {
            int c = c0 + tx * 4 + j;
            g_y[((size_t)b * T + t) * C + c] = acc[i][j];
        }
    }
}

// ---------------------------------------------------------------------------
// vsum[b,c] = sum_t v[b,t,c]
// ---------------------------------------------------------------------------
__global__ void vsum_kernel() {
    const int b = blockIdx.y;
    const int c = blockIdx.x * 256 + threadIdx.x;
    float s = 0.0f;
    for (int t = 0; t < T; ++t) s += g_v[((size_t)b * T + t) * C + c];
    g_vsum[b * C + c] = s;
}

// ---------------------------------------------------------------------------
// vsumWl[b] = dot(vsum[b], Wl)
// ---------------------------------------------------------------------------
__global__ void vsumwl_kernel(const float* __restrict__ Wl) {
    __shared__ float red[128];
    const int b = blockIdx.x;
    const int tid = threadIdx.x;
    float s = 0.0f;
    for (int c = tid; c < C; c += 128) s += g_vsum[b * C + c] * Wl[c];
    red[tid] = s;
    __syncthreads();
    for (int off = 64; off > 0; off >>= 1) {
        if (tid < off) red[tid] += red[tid + off];
        __syncthreads();
    }
    if (tid == 0) g_vsumWl[b] = red[0];
}

// ---------------------------------------------------------------------------
// f_score: per (b,t)
//   yl = dot(y[b,t,:], Wl); zl = vsumWl[b] - yl
//   score = 0.5*(sigmoid(yl+bl) + 1 - sigmoid(zl+bl))
// ---------------------------------------------------------------------------
__global__ void score_kernel(const float* __restrict__ Wl,
                             const float* __restrict__ bl,
                             float* __restrict__ score) {
    __shared__ float red[128];
    const int row = blockIdx.x;  // b*T + t
    const int b = row / T;
    const int tid = threadIdx.x;
    const float* yr = g_y + (size_t)row * C;
    float s = 0.0f;
    for (int c = tid; c < C; c += 128) s += yr[c] * Wl[c];
    red[tid] = s;
    __syncthreads();
    for (int off = 64; off > 0; off >>= 1) {
        if (tid < off) red[tid] += red[tid + off];
        __syncthreads();
    }
    if (tid == 0) {
        float yl = red[0];
        float zl = g_vsumWl[b] - yl;
        float b0 = bl[0];
        float fs = sigmoidf_(yl + b0);
        float bs = 1.0f - sigmoidf_(zl + b0);
        score[row] = 0.5f * (fs + bs);
    }
}

// ---------------------------------------------------------------------------
// Smooth conv + residual: out[b,o,t] = feat[b,o,t] + sum_c Ws[o,c]*y[b,t,c] + bs[o]
// (pre-LayerNorm, written directly to d_out)
// ---------------------------------------------------------------------------
__global__ void smooth_kernel(const float* __restrict__ Ws,
                              const float* __restrict__ bs,
                              const float* __restrict__ feat,
                              float* __restrict__ out) {
    __shared__ float As[16][64];  // [c][o]
    __shared__ float Bs[16][64];  // [c][t]
    const int b  = blockIdx.z;
    const int t0 = blockIdx.x * 64;
    const int o0 = blockIdx.y * 64;
    const int tid = threadIdx.x;
    const int tx = tid & 15, ty = tid >> 4;

    float acc[4][4] = {};
    for (int c0 = 0; c0 < C; c0 += 16) {
#pragma unroll
        for (int p = 0; p < 4; ++p) {
            int idx = p * 256 + tid;
            As[idx & 15][idx >> 4] = Ws[(size_t)(o0 + (idx >> 4)) * C + c0 + (idx & 15)];
            Bs[idx & 15][idx >> 4] = g_y[((size_t)b * T + t0 + (idx >> 4)) * C + c0 + (idx & 15)];
        }
        __syncthreads();
#pragma unroll
        for (int kk = 0; kk < 16; ++kk) {
            float4 av = *reinterpret_cast<const float4*>(&As[kk][ty * 4]);
            float4 bv = *reinterpret_cast<const float4*>(&Bs[kk][tx * 4]);
            float a[4] = {av.x, av.y, av.z, av.w};
            float bb[4] = {bv.x, bv.y, bv.z, bv.w};
#pragma unroll
            for (int i = 0; i < 4; ++i)
#pragma unroll
                for (int j = 0; j < 4; ++j) acc[i][j] += a[i] * bb[j];
        }
        __syncthreads();
    }
#pragma unroll
    for (int i = 0; i < 4; ++i) {
        int o = o0 + ty * 4 + i;
        float bo = bs[o];
#pragma unroll
        for (int j = 0; j < 4; ++j) {
            int t = t0 + tx * 4 + j;
            size_t oi = ((size_t)b * C + o) * T + t;
            out[oi] = feat[oi] + acc[i][j] + bo;
        }
    }
}

// ---------------------------------------------------------------------------
// LayerNorm pass 1: per-batch sum & sumsq over C*T elements
// ---------------------------------------------------------------------------
__global__ void ln1_kernel(const float* __restrict__ out) {
    __shared__ double rs[256];
    __shared__ double rq[256];
    const int b = blockIdx.y;
    const float* p = out + (size_t)b * C * T;
    const int n = C * T;
    const int tid = threadIdx.x;
    double ls = 0.0, lq = 0.0;
    for (int i = blockIdx.x * 256 + tid; i < n; i += gridDim.x * 256) {
        float x = p[i];
        ls += (double)x;
        lq += (double)x * (double)x;
    }
    rs[tid] = ls;
    rq[tid] = lq;
    __syncthreads();
    for (int off = 128; off > 0; off >>= 1) {
        if (tid < off) { rs[tid] += rs[tid + off]; rq[tid] += rq[tid + off]; }
        __syncthreads();
    }
    if (tid == 0) {
        atomicAdd(&g_lnsum[b], rs[0]);
        atomicAdd(&g_lnsq[b], rq[0]);
    }
}

// ---------------------------------------------------------------------------
// LayerNorm pass 2: normalize in place
// ---------------------------------------------------------------------------
__global__ void ln2_kernel(float* __restrict__ out) {
    const int b = blockIdx.y;
    const int i = blockIdx.x * 256 + threadIdx.x;
    const double n = (double)(C * T);
    double mu = g_lnsum[b] / n;
    double var = g_lnsq[b] / n - mu * mu;
    float muf = (float)mu;
    float inv = rsqrtf((float)var + LN_EPS);
    size_t oi = (size_t)b * C * T + i;
    out[oi] = (out[oi] - muf) * inv;
}

}  // namespace

// ---------------------------------------------------------------------------
// Launch
// ---------------------------------------------------------------------------
extern "C" void kernel_launch(void* const* d_in, const int* in_sizes, int n_in,
                              void* d_out, int out_size) {
    const float* feat = (const float*)d_in[0];
    const float* Wq   = (const float*)d_in[1];
    const float* bq   = (const float*)d_in[2];
    const float* Wk   = (const float*)d_in[3];
    const float* bk   = (const float*)d_in[4];
    const float* Wv   = (const float*)d_in[5];
    const float* bv   = (const float*)d_in[6];
    const float* Ws   = (const float*)d_in[7];
    const float* bs   = (const float*)d_in[8];
    const float* Wl   = (const float*)d_in[9];
    const float* bl   = (const float*)d_in[10];
    float* out = (float*)d_out;
    float* score = out + (size_t)B * C * T;

    float *qp, *vp;
    cudaGetSymbolAddress((void**)&qp, g_q);
    cudaGetSymbolAddress((void**)&vp, g_v);

    zero_kernel<<<1, 32>>>();
    wksum_kernel<<<2, 256>>>(Wk);
    kscale_kernel<<<(B * C * T) / 256, 256>>>(feat, bk);

    dim3 gproj(T / 64, C / 64, B);  // (32, 8, 4)
    proj_kernel<<<gproj, 256>>>(Wq, bq, feat, qp);
    proj_kernel<<<gproj, 256>>>(Wv, bv, feat, vp);

    dim3 gqk(T / 64, T / 64, B);    // (32, 32, 4)
    qk_kernel<<<gqk, 256>>>();

    softmax_kernel<<<B * T, 256>>>();

    dim3 gav(C / 64, T / 64, B);    // (8, 32, 4)
    av_kernel<<<gav, 256>>>();

    vsum_kernel<<<dim3(C / 256, B), 256>>>();
    vsumwl_kernel<<<B, 128>>>(Wl);
    score_kernel<<<B * T, 128>>>(Wl, bl, score);

    smooth_kernel<<<gproj, 256>>>(Ws, bs, feat, out);

    ln1_kernel<<<dim3(64, B), 256>>>(out);
    ln2_kernel<<<dim3((C * T) / 256, B), 256>>>(out);
}

// round 3
// speedup vs baseline: 3.2322x; 3.2322x over previous
#include <cuda_runtime.h>
#include <cuda_bf16.h>
#include <math.h>
#include <stdint.h>

// ---------------------------------------------------------------------------
// ForegroundAttentionModule, B=4, C=512, T=2048, fp32 in/out.
// Tensor-core path via mma.sync (sm_80 PTX -> legal under compute_103),
// split-bf16 (hi+lo, 3 products) for ~fp32 accuracy.
//   key_ einsum collapses to elementwise scale; z = colsum(v) - y.
// GEMM: D[M,N] = sum_K A[M,K]*B[N,K]. CTA tile 128x128, K chunk 32,
// cp.async double buffer, 8 warps (4 M x 2 N), warp tile 32x64.
// ---------------------------------------------------------------------------

namespace {

constexpr int B = 4;
constexpr int C = 512;
constexpr int T = 2048;
constexpr float LN_EPS = 1e-5f;
constexpr float INV_SQRT_C = 0.04419417382415922f;

// smem tile geometry: 128 rows x 32 bf16, row stride padded to 20 words (80B)
constexpr int ROW_WORDS   = 20;
constexpr int TILE_WORDS  = 128 * ROW_WORDS;        // 2560 words = 10240 B
constexpr int STAGE_WORDS = 4 * TILE_WORDS;         // Ah, Al, Bh, Bl
constexpr int SMEM_WORDS  = 2 * STAGE_WORDS;        // double buffer
constexpr int SMEM_BYTES  = SMEM_WORDS * 4;         // 81920 B

// ---------------- device scratch (no runtime allocation allowed) -----------
__device__ __nv_bfloat16 g_featT_h[(size_t)B * T * C];
__device__ __nv_bfloat16 g_featT_l[(size_t)B * T * C];
__device__ __nv_bfloat16 g_kT_h[(size_t)B * T * C];
__device__ __nv_bfloat16 g_kT_l[(size_t)B * T * C];
__device__ __nv_bfloat16 g_q_h[(size_t)B * T * C];
__device__ __nv_bfloat16 g_q_l[(size_t)B * T * C];
__device__ __nv_bfloat16 g_vT_h[(size_t)B * C * T];
__device__ __nv_bfloat16 g_vT_l[(size_t)B * C * T];
__device__ __nv_bfloat16 g_y_h[(size_t)B * T * C];
__device__ __nv_bfloat16 g_y_l[(size_t)B * T * C];
__device__ __nv_bfloat16 g_f_h[(size_t)B * T * T];
__device__ __nv_bfloat16 g_f_l[(size_t)B * T * T];
__device__ float g_f[(size_t)B * T * T];
__device__ float g_y[(size_t)B * T * C];
__device__ __nv_bfloat16 g_Wq_h[C * C], g_Wq_l[C * C];
__device__ __nv_bfloat16 g_Wv_h[C * C], g_Wv_l[C * C];
__device__ __nv_bfloat16 g_Ws_h[C * C], g_Ws_l[C * C];
__device__ float  g_wksum[C];
__device__ float  g_vsum[B * C];
__device__ float  g_vsumWl[B];
__device__ double g_lnsum[B], g_lnsq[B];

// ---------------- helpers ---------------------------------------------------
__device__ __forceinline__ void split2(float v, __nv_bfloat16& h, __nv_bfloat16& l) {
    h = __float2bfloat16(v);
    l = __float2bfloat16(v - __bfloat162float(h));
}

__device__ __forceinline__ void mma16816(float* c, uint32_t a0, uint32_t a1,
                                         uint32_t a2, uint32_t a3,
                                         uint32_t b0, uint32_t b1) {
    asm volatile(
        "mma.sync.aligned.m16n8k16.row.col.f32.bf16.bf16.f32 "
        "{%0,%1,%2,%3}, {%4,%5,%6,%7}, {%8,%9}, {%0,%1,%2,%3};"
        : "+f"(c[0]), "+f"(c[1]), "+f"(c[2]), "+f"(c[3])
        : "r"(a0), "r"(a1), "r"(a2), "r"(a3), "r"(b0), "r"(b1));
}

__device__ __forceinline__ void cp_async16(uint32_t saddr, const void* g) {
    asm volatile("cp.async.cg.shared.global [%0], [%1], 16;" ::"r"(saddr), "l"(g));
}
__device__ __forceinline__ void cp_commit() {
    asm volatile("cp.async.commit_group;" ::: "memory");
}
template <int N>
__device__ __forceinline__ void cp_wait() {
    asm volatile("cp.async.wait_group %0;" ::"n"(N) : "memory");
}

// Issue async copies for one 128x32 bf16 tile (2 x 16B per thread).
__device__ __forceinline__ void load_tile(const __nv_bfloat16* __restrict__ src,
                                          int ld, int k0, uint32_t sbase, int tid) {
#pragma unroll
    for (int p = 0; p < 2; ++p) {
        int i = tid + p * 256;
        int row = i >> 2, q = i & 3;
        cp_async16(sbase + (uint32_t)(row * ROW_WORDS + q * 4) * 4,
                   src + (size_t)row * ld + k0 + q * 8);
    }
}

// ---------------------------------------------------------------------------
// GEMM mainloop: accumulates D tile (128x128) into registers.
// acc[am][an][4]: warp (wm=wid&3 rows 32, wn=wid>>2 cols 64), 2 m-atoms x 8 n-atoms.
// ---------------------------------------------------------------------------
__device__ __forceinline__ void gemm_mainloop(
    const __nv_bfloat16* __restrict__ Ah, const __nv_bfloat16* __restrict__ Al, int ldA,
    const __nv_bfloat16* __restrict__ Bh, const __nv_bfloat16* __restrict__ Bl, int ldB,
    int kTotal, uint32_t* smem, float acc[2][8][4]) {
    const int tid = threadIdx.x;
    const int wid = tid >> 5, lane = tid & 31;
    const int wm = wid & 3, wn = wid >> 2;
    const int lr = lane >> 2, lc = lane & 3;
    const uint32_t sbase = (uint32_t)__cvta_generic_to_shared(smem);
    const int nch = kTotal / 32;

    // prologue: chunk 0 -> stage 0
    load_tile(Ah, ldA, 0, sbase + 0 * TILE_WORDS * 4, tid);
    load_tile(Al, ldA, 0, sbase + 1 * TILE_WORDS * 4, tid);
    load_tile(Bh, ldB, 0, sbase + 2 * TILE_WORDS * 4, tid);
    load_tile(Bl, ldB, 0, sbase + 3 * TILE_WORDS * 4, tid);
    cp_commit();

    for (int kc = 0; kc < nch; ++kc) {
        if (kc + 1 < nch) {
            uint32_t st = sbase + (uint32_t)(((kc + 1) & 1) * STAGE_WORDS) * 4;
            int k0 = (kc + 1) * 32;
            load_tile(Ah, ldA, k0, st + 0 * TILE_WORDS * 4, tid);
            load_tile(Al, ldA, k0, st + 1 * TILE_WORDS * 4, tid);
            load_tile(Bh, ldB, k0, st + 2 * TILE_WORDS * 4, tid);
            load_tile(Bl, ldB, k0, st + 3 * TILE_WORDS * 4, tid);
            cp_commit();
            cp_wait<1>();
        } else {
            cp_wait<0>();
        }
        __syncthreads();

        const uint32_t* sAh = smem + (kc & 1) * STAGE_WORDS;
        const uint32_t* sAl = sAh + TILE_WORDS;
        const uint32_t* sBh = sAh + 2 * TILE_WORDS;
        const uint32_t* sBl = sAh + 3 * TILE_WORDS;

#pragma unroll
        for (int ks = 0; ks < 2; ++ks) {
            const int w = ks * 8 + lc;
            uint32_t ah[2][4], al[2][4];
#pragma unroll
            for (int am = 0; am < 2; ++am) {
                const int r = wm * 32 + am * 16 + lr;
                ah[am][0] = sAh[r * ROW_WORDS + w];
                ah[am][1] = sAh[(r + 8) * ROW_WORDS + w];
                ah[am][2] = sAh[r * ROW_WORDS + w + 4];
                ah[am][3] = sAh[(r + 8) * ROW_WORDS + w + 4];
                al[am][0] = sAl[r * ROW_WORDS + w];
                al[am][1] = sAl[(r + 8) * ROW_WORDS + w];
                al[am][2] = sAl[r * ROW_WORDS + w + 4];
                al[am][3] = sAl[(r + 8) * ROW_WORDS + w + 4];
            }
#pragma unroll
            for (int an = 0; an < 8; ++an) {
                const int n = wn * 64 + an * 8 + lr;
                uint32_t bh0 = sBh[n * ROW_WORDS + w];
                uint32_t bh1 = sBh[n * ROW_WORDS + w + 4];
                uint32_t bl0 = sBl[n * ROW_WORDS + w];
                uint32_t bl1 = sBl[n * ROW_WORDS + w + 4];
#pragma unroll
                for (int am = 0; am < 2; ++am) {
                    mma16816(acc[am][an], ah[am][0], ah[am][1], ah[am][2], ah[am][3], bh0, bh1);
                    mma16816(acc[am][an], ah[am][0], ah[am][1], ah[am][2], ah[am][3], bl0, bl1);
                    mma16816(acc[am][an], al[am][0], al[am][1], al[am][2], al[am][3], bh0, bh1);
                }
            }
        }
        __syncthreads();
    }
}

// Epilogue coordinate helper: local row pair base, local col for (am, an).
#define EPI_COORDS()                                   \
    const int wid = threadIdx.x >> 5;                  \
    const int lane = threadIdx.x & 31;                 \
    const int wm = wid & 3, wn = wid >> 2;             \
    const int lr = lane >> 2, lc = lane & 3;

// ---------------------------------------------------------------------------
// GEMM kernels
// ---------------------------------------------------------------------------

// q[b,t,o] = featT @ Wq^T + bq  -> split bf16
__global__ __launch_bounds__(256) void gemm_q_kernel(const float* __restrict__ bq) {
    extern __shared__ uint32_t smem[];
    const int b = blockIdx.z, t0 = blockIdx.x * 128, o0 = blockIdx.y * 128;
    float acc[2][8][4] = {};
    gemm_mainloop(g_featT_h + ((size_t)b * T + t0) * C, g_featT_l + ((size_t)b * T + t0) * C, C,
                  g_Wq_h + (size_t)o0 * C, g_Wq_l + (size_t)o0 * C, C, C, smem, acc);
    EPI_COORDS();
#pragma unroll
    for (int am = 0; am < 2; ++am) {
        const int t = t0 + wm * 32 + am * 16 + lr;
#pragma unroll
        for (int an = 0; an < 8; ++an) {
            const int o = o0 + wn * 64 + an * 8 + lc * 2;
            const float b0 = bq[o], b1 = bq[o + 1];
#pragma unroll
            for (int rr = 0; rr < 2; ++rr) {
                const size_t idx = ((size_t)b * T + t + rr * 8) * C + o;
                float v0 = acc[am][an][rr * 2] + b0;
                float v1 = acc[am][an][rr * 2 + 1] + b1;
                __nv_bfloat16 h0, l0, h1, l1;
                split2(v0, h0, l0); split2(v1, h1, l1);
                *reinterpret_cast<__nv_bfloat162*>(&g_q_h[idx]) = __halves2bfloat162(h0, h1);
                *reinterpret_cast<__nv_bfloat162*>(&g_q_l[idx]) = __halves2bfloat162(l0, l1);
            }
        }
    }
}

// vT[b,o,t] = Wv @ featT^T + bv  -> split bf16 (t-contiguous)
__global__ __launch_bounds__(256) void gemm_vt_kernel(const float* __restrict__ bv) {
    extern __shared__ uint32_t smem[];
    const int b = blockIdx.z, t0 = blockIdx.x * 128, o0 = blockIdx.y * 128;
    float acc[2][8][4] = {};
    gemm_mainloop(g_Wv_h + (size_t)o0 * C, g_Wv_l + (size_t)o0 * C, C,
                  g_featT_h + ((size_t)b * T + t0) * C, g_featT_l + ((size_t)b * T + t0) * C, C,
                  C, smem, acc);
    EPI_COORDS();
#pragma unroll
    for (int am = 0; am < 2; ++am) {
        const int o = o0 + wm * 32 + am * 16 + lr;
#pragma unroll
        for (int an = 0; an < 8; ++an) {
            const int t = t0 + wn * 64 + an * 8 + lc * 2;
#pragma unroll
            for (int rr = 0; rr < 2; ++rr) {
                const int oo = o + rr * 8;
                const float bo = bv[oo];
                const size_t idx = ((size_t)b * C + oo) * T + t;
                float v0 = acc[am][an][rr * 2] + bo;
                float v1 = acc[am][an][rr * 2 + 1] + bo;
                __nv_bfloat16 h0, l0, h1, l1;
                split2(v0, h0, l0); split2(v1, h1, l1);
                *reinterpret_cast<__nv_bfloat162*>(&g_vT_h[idx]) = __halves2bfloat162(h0, h1);
                *reinterpret_cast<__nv_bfloat162*>(&g_vT_l[idx]) = __halves2bfloat162(l0, l1);
            }
        }
    }
}

// f[b,t,s] = (q @ kT^T) * inv_sqrt_c   (fp32)
__global__ __launch_bounds__(256) void gemm_qk_kernel() {
    extern __shared__ uint32_t smem[];
    const int b = blockIdx.z, s0 = blockIdx.x * 128, t0 = blockIdx.y * 128;
    float acc[2][8][4] = {};
    gemm_mainloop(g_q_h + ((size_t)b * T + t0) * C, g_q_l + ((size_t)b * T + t0) * C, C,
                  g_kT_h + ((size_t)b * T + s0) * C, g_kT_l + ((size_t)b * T + s0) * C, C,
                  C, smem, acc);
    EPI_COORDS();
#pragma unroll
    for (int am = 0; am < 2; ++am) {
        const int t = t0 + wm * 32 + am * 16 + lr;
#pragma unroll
        for (int an = 0; an < 8; ++an) {
            const int s = s0 + wn * 64 + an * 8 + lc * 2;
#pragma unroll
            for (int rr = 0; rr < 2; ++rr) {
                float2 v;
                v.x = acc[am][an][rr * 2] * INV_SQRT_C;
                v.y = acc[am][an][rr * 2 + 1] * INV_SQRT_C;
                *reinterpret_cast<float2*>(&g_f[((size_t)b * T + t + rr * 8) * T + s]) = v;
            }
        }
    }
}

// y[b,t,c] = f @ vT^T   (fp32 + split bf16)
__global__ __launch_bounds__(256) void gemm_av_kernel() {
    extern __shared__ uint32_t smem[];
    const int b = blockIdx.z, c0 = blockIdx.x * 128, t0 = blockIdx.y * 128;
    float acc[2][8][4] = {};
    gemm_mainloop(g_f_h + ((size_t)b * T + t0) * T, g_f_l + ((size_t)b * T + t0) * T, T,
                  g_vT_h + ((size_t)b * C + c0) * T, g_vT_l + ((size_t)b * C + c0) * T, T,
                  T, smem, acc);
    EPI_COORDS();
#pragma unroll
    for (int am = 0; am < 2; ++am) {
        const int t = t0 + wm * 32 + am * 16 + lr;
#pragma unroll
        for (int an = 0; an < 8; ++an) {
            const int c = c0 + wn * 64 + an * 8 + lc * 2;
#pragma unroll
            for (int rr = 0; rr < 2; ++rr) {
                const size_t idx = ((size_t)b * T + t + rr * 8) * C + c;
                float v0 = acc[am][an][rr * 2];
                float v1 = acc[am][an][rr * 2 + 1];
                *reinterpret_cast<float2*>(&g_y[idx]) = make_float2(v0, v1);
                __nv_bfloat16 h0, l0, h1, l1;
                split2(v0, h0, l0); split2(v1, h1, l1);
                *reinterpret_cast<__nv_bfloat162*>(&g_y_h[idx]) = __halves2bfloat162(h0, h1);
                *reinterpret_cast<__nv_bfloat162*>(&g_y_l[idx]) = __halves2bfloat162(l0, l1);
            }
        }
    }
}

// out[b,o,t] = feat + Ws @ y^T + bs   (fp32, pre-LN)
__global__ __launch_bounds__(256) void gemm_smooth_kernel(const float* __restrict__ bs,
                                                          const float* __restrict__ feat,
                                                          float* __restrict__ out) {
    extern __shared__ uint32_t smem[];
    const int b = blockIdx.z, t0 = blockIdx.x * 128, o0 = blockIdx.y * 128;
    float acc[2][8][4] = {};
    gemm_mainloop(g_Ws_h + (size_t)o0 * C, g_Ws_l + (size_t)o0 * C, C,
                  g_y_h + ((size_t)b * T + t0) * C, g_y_l + ((size_t)b * T + t0) * C, C,
                  C, smem, acc);
    EPI_COORDS();
#pragma unroll
    for (int am = 0; am < 2; ++am) {
        const int o = o0 + wm * 32 + am * 16 + lr;
#pragma unroll
        for (int an = 0; an < 8; ++an) {
            const int t = t0 + wn * 64 + an * 8 + lc * 2;
#pragma unroll
            for (int rr = 0; rr < 2; ++rr) {
                const int oo = o + rr * 8;
                const float bo = bs[oo];
                const size_t idx = ((size_t)b * C + oo) * T + t;
                float2 fv = *reinterpret_cast<const float2*>(&feat[idx]);
                float2 v;
                v.x = fv.x + acc[am][an][rr * 2] + bo;
                v.y = fv.y + acc[am][an][rr * 2 + 1] + bo;
                *reinterpret_cast<float2*>(&out[idx]) = v;
            }
        }
    }
}

// ---------------------------------------------------------------------------
// Elementwise / reduction kernels
// ---------------------------------------------------------------------------
__global__ void zero_kernel() {
    int i = threadIdx.x;
    if (i < B) { g_lnsum[i] = 0.0; g_lnsq[i] = 0.0; }
}

__global__ void wksum_kernel(const float* __restrict__ Wk) {
    int c = blockIdx.x * 256 + threadIdx.x;
    if (c >= C) return;
    float s = 0.0f;
    for (int o = 0; o < C; ++o) s += Wk[(size_t)o * C + c];
    g_wksum[c] = s;
}

// feat [B,C,T] -> featT split [B,T,C]; kT split = wksum*feat + bk
__global__ void transpose_split_kernel(const float* __restrict__ feat,
                                       const float* __restrict__ bk) {
    __shared__ float tile[32][33];
    const int b = blockIdx.z;
    const int t0 = blockIdx.x * 32, c0 = blockIdx.y * 32;
    const int tx = threadIdx.x, ty = threadIdx.y;
#pragma unroll
    for (int i = 0; i < 4; ++i)
        tile[ty + 8 * i][tx] = feat[((size_t)b * C + c0 + ty + 8 * i) * T + t0 + tx];
    __syncthreads();
    const int c = c0 + tx;
    const float wk = g_wksum[c], bkc = bk[c];
#pragma unroll
    for (int i = 0; i < 4; ++i) {
        const int t = t0 + ty + 8 * i;
        const float v = tile[tx][ty + 8 * i];
        const size_t idx = ((size_t)b * T + t) * C + c;
        __nv_bfloat16 h, l;
        split2(v, h, l);
        g_featT_h[idx] = h; g_featT_l[idx] = l;
        const float kv = wk * v + bkc;
        split2(kv, h, l);
        g_kT_h[idx] = h; g_kT_l[idx] = l;
    }
}

__global__ void splitw_kernel(const float* __restrict__ Wq,
                              const float* __restrict__ Wv,
                              const float* __restrict__ Ws) {
    int i = blockIdx.x * 256 + threadIdx.x;
    if (i >= C * C) return;
    __nv_bfloat16 h, l;
    split2(Wq[i], h, l); g_Wq_h[i] = h; g_Wq_l[i] = l;
    split2(Wv[i], h, l); g_Wv_h[i] = h; g_Wv_l[i] = l;
    split2(Ws[i], h, l); g_Ws_h[i] = h; g_Ws_l[i] = l;
}

// Row softmax over s, writes split bf16 probabilities.
__global__ void softmax_kernel() {
    __shared__ float buf[T];
    __shared__ float red[256];
    const size_t base = (size_t)blockIdx.x * T;  // b*T + t
    const int tid = threadIdx.x;
    float m = -1e30f;
    for (int s = tid; s < T; s += 256) {
        float x = g_f[base + s];
        buf[s] = x;
        m = fmaxf(m, x);
    }
    red[tid] = m;
    __syncthreads();
    for (int off = 128; off > 0; off >>= 1) {
        if (tid < off) red[tid] = fmaxf(red[tid], red[tid + off]);
        __syncthreads();
    }
    m = red[0];
    __syncthreads();
    float sum = 0.0f;
    for (int s = tid; s < T; s += 256) {
        float e = __expf(buf[s] - m);
        buf[s] = e;
        sum += e;
    }
    red[tid] = sum;
    __syncthreads();
    for (int off = 128; off > 0; off >>= 1) {
        if (tid < off) red[tid] += red[tid + off];
        __syncthreads();
    }
    const float inv = 1.0f / red[0];
    for (int s = tid * 2; s < T; s += 512) {
        float p0 = buf[s] * inv, p1 = buf[s + 1] * inv;
        __nv_bfloat16 h0, l0, h1, l1;
        split2(p0, h0, l0); split2(p1, h1, l1);
        *reinterpret_cast<__nv_bfloat162*>(&g_f_h[base + s]) = __halves2bfloat162(h0, h1);
        *reinterpret_cast<__nv_bfloat162*>(&g_f_l[base + s]) = __halves2bfloat162(l0, l1);
    }
}

__global__ void vsum_kernel() {
    __shared__ float red[256];
    const int c = blockIdx.x, b = blockIdx.y, tid = threadIdx.x;
    const __nv_bfloat16* ph = g_vT_h + ((size_t)b * C + c) * T;
    const __nv_bfloat16* pl = g_vT_l + ((size_t)b * C + c) * T;
    float s = 0.0f;
    for (int t = tid; t < T; t += 256)
        s += __bfloat162float(ph[t]) + __bfloat162float(pl[t]);
    red[tid] = s;
    __syncthreads();
    for (int off = 128; off > 0; off >>= 1) {
        if (tid < off) red[tid] += red[tid + off];
        __syncthreads();
    }
    if (tid == 0) g_vsum[b * C + c] = red[0];
}

__global__ void vsumwl_kernel(const float* __restrict__ Wl) {
    __shared__ float red[128];
    const int b = blockIdx.x, tid = threadIdx.x;
    float s = 0.0f;
    for (int c = tid; c < C; c += 128) s += g_vsum[b * C + c] * Wl[c];
    red[tid] = s;
    __syncthreads();
    for (int off = 64; off > 0; off >>= 1) {
        if (tid < off) red[tid] += red[tid + off];
        __syncthreads();
    }
    if (tid == 0) g_vsumWl[b] = red[0];
}

__global__ void score_kernel(const float* __restrict__ Wl,
                             const float* __restrict__ bl,
                             float* __restrict__ score) {
    __shared__ float red[128];
    const int row = blockIdx.x;  // b*T + t
    const int b = row / T;
    const int tid = threadIdx.x;
    const float* yr = g_y + (size_t)row * C;
    float s = 0.0f;
    for (int c = tid; c < C; c += 128) s += yr[c] * Wl[c];
    red[tid] = s;
    __syncthreads();
    for (int off = 64; off > 0; off >>= 1) {
        if (tid < off) red[tid] += red[tid + off];
        __syncthreads();
    }
    if (tid == 0) {
        float yl = red[0];
        float zl = g_vsumWl[b] - yl;
        float b0 = bl[0];
        float fs = 1.0f / (1.0f + expf(-(yl + b0)));
        float bsc = 1.0f - 1.0f / (1.0f + expf(-(zl + b0)));
        score[row] = 0.5f * (fs + bsc);
    }
}

__global__ void ln1_kernel(const float* __restrict__ out) {
    __shared__ double rs[256];
    __shared__ double rq[256];
    const int b = blockIdx.y;
    const float* p = out + (size_t)b * C * T;
    const int n = C * T;
    const int tid = threadIdx.x;
    double ls = 0.0, lq = 0.0;
    for (int i = blockIdx.x * 256 + tid; i < n; i += gridDim.x * 256) {
        float x = p[i];
        ls += (double)x;
        lq += (double)x * (double)x;
    }
    rs[tid] = ls; rq[tid] = lq;
    __syncthreads();
    for (int off = 128; off > 0; off >>= 1) {
        if (tid < off) { rs[tid] += rs[tid + off]; rq[tid] += rq[tid + off]; }
        __syncthreads();
    }
    if (tid == 0) {
        atomicAdd(&g_lnsum[b], rs[0]);
        atomicAdd(&g_lnsq[b], rq[0]);
    }
}

__global__ void ln2_kernel(float* __restrict__ out) {
    const int b = blockIdx.y;
    const int i = blockIdx.x * 256 + threadIdx.x;
    const double n = (double)(C * T);
    double mu = g_lnsum[b] / n;
    double var = g_lnsq[b] / n - mu * mu;
    float muf = (float)mu;
    float inv = rsqrtf((float)var + LN_EPS);
    size_t oi = (size_t)b * C * T + i;
    out[oi] = (out[oi] - muf) * inv;
}

}  // namespace

// ---------------------------------------------------------------------------
extern "C" void kernel_launch(void* const* d_in, const int* in_sizes, int n_in,
                              void* d_out, int out_size) {
    const float* feat = (const float*)d_in[0];
    const float* Wq   = (const float*)d_in[1];
    const float* bq   = (const float*)d_in[2];
    const float* Wk   = (const float*)d_in[3];
    const float* bk   = (const float*)d_in[4];
    const float* Wv   = (const float*)d_in[5];
    const float* bv   = (const float*)d_in[6];
    const float* Ws   = (const float*)d_in[7];
    const float* bs   = (const float*)d_in[8];
    const float* Wl   = (const float*)d_in[9];
    const float* bl   = (const float*)d_in[10];
    float* out = (float*)d_out;
    float* score = out + (size_t)B * C * T;

    cudaFuncSetAttribute(gemm_q_kernel,      cudaFuncAttributeMaxDynamicSharedMemorySize, SMEM_BYTES);
    cudaFuncSetAttribute(gemm_vt_kernel,     cudaFuncAttributeMaxDynamicSharedMemorySize, SMEM_BYTES);
    cudaFuncSetAttribute(gemm_qk_kernel,     cudaFuncAttributeMaxDynamicSharedMemorySize, SMEM_BYTES);
    cudaFuncSetAttribute(gemm_av_kernel,     cudaFuncAttributeMaxDynamicSharedMemorySize, SMEM_BYTES);
    cudaFuncSetAttribute(gemm_smooth_kernel, cudaFuncAttributeMaxDynamicSharedMemorySize, SMEM_BYTES);

    zero_kernel<<<1, 32>>>();
    wksum_kernel<<<2, 256>>>(Wk);
    transpose_split_kernel<<<dim3(T / 32, C / 32, B), dim3(32, 8)>>>(feat, bk);
    splitw_kernel<<<(C * C + 255) / 256, 256>>>(Wq, Wv, Ws);

    gemm_q_kernel<<<dim3(T / 128, C / 128, B), 256, SMEM_BYTES>>>(bq);
    gemm_vt_kernel<<<dim3(T / 128, C / 128, B), 256, SMEM_BYTES>>>(bv);
    gemm_qk_kernel<<<dim3(T / 128, T / 128, B), 256, SMEM_BYTES>>>();
    softmax_kernel<<<B * T, 256>>>();
    gemm_av_kernel<<<dim3(C / 128, T / 128, B), 256, SMEM_BYTES>>>();

    vsum_kernel<<<dim3(C, B), 256>>>();
    vsumwl_kernel<<<B, 128>>>(Wl);
    score_kernel<<<B * T, 128>>>(Wl, bl, score);

    gemm_smooth_kernel<<<dim3(T / 128, C / 128, B), 256, SMEM_BYTES>>>(bs, feat, out);

    ln1_kernel<<<dim3(64, B), 256>>>(out);
    ln2_kernel<<<dim3((C * T) / 256, B), 256>>>(out);
}

// round 4
// speedup vs baseline: 3.6744x; 1.1368x over previous
#include <cuda_runtime.h>
#include <cuda_fp16.h>
#include <math.h>
#include <stdint.h>

// ---------------------------------------------------------------------------
// ForegroundAttentionModule, B=4, C=512, T=2048, fp32 in/out.
// Tensor cores via mma.sync m16n8k16 fp16 (f32 accum), SINGLE product per
// GEMM (norm-level error ~4e-4 at GEMM, diluted ~25x by residual+LN).
//   key_ einsum collapses to elementwise scale; z = colsum(v) - y.
// GEMM: D[M,N] = sum_K A[M,K]*B[N,K]. CTA tile 128x128, K chunk 32,
// cp.async double buffer, 8 warps (4 M x 2 N), warp tile 32x64.
// ---------------------------------------------------------------------------

namespace {

constexpr int B = 4;
constexpr int C = 512;
constexpr int T = 2048;
constexpr float LN_EPS = 1e-5f;
constexpr float INV_SQRT_C = 0.04419417382415922f;

// smem tile geometry: 128 rows x 32 fp16, row stride padded to 20 words (80B)
constexpr int ROW_WORDS   = 20;
constexpr int TILE_WORDS  = 128 * ROW_WORDS;   // 2560 words = 10240 B
constexpr int STAGE_WORDS = 2 * TILE_WORDS;    // A, B
constexpr int SMEM_WORDS  = 2 * STAGE_WORDS;   // double buffer
constexpr int SMEM_BYTES  = SMEM_WORDS * 4;    // 40960 B

// ---------------- device scratch (no runtime allocation allowed) -----------
__device__ __half g_featT[(size_t)B * T * C];   // [B,T,C]
__device__ __half g_kT[(size_t)B * T * C];      // [B,T,C] (s-major rows)
__device__ __half g_q[(size_t)B * T * C];       // [B,T,C]
__device__ __half g_vT[(size_t)B * C * T];      // [B,C,T]
__device__ __half g_y[(size_t)B * T * C];       // [B,T,C]
__device__ __half g_fh[(size_t)B * T * T];      // [B,T,T] logits -> probs in place
__device__ __half g_Wq[C * C], g_Wv[C * C], g_Ws[C * C];
__device__ float  g_wksum[C];
__device__ float  g_vsum[B * C];
__device__ float  g_vsumWl[B];
__device__ double g_lnsum[B], g_lnsq[B];

// ---------------- helpers ---------------------------------------------------
__device__ __forceinline__ void mma16816(float* c, uint32_t a0, uint32_t a1,
                                         uint32_t a2, uint32_t a3,
                                         uint32_t b0, uint32_t b1) {
    asm volatile(
        "mma.sync.aligned.m16n8k16.row.col.f32.f16.f16.f32 "
        "{%0,%1,%2,%3}, {%4,%5,%6,%7}, {%8,%9}, {%0,%1,%2,%3};"
        : "+f"(c[0]), "+f"(c[1]), "+f"(c[2]), "+f"(c[3])
        : "r"(a0), "r"(a1), "r"(a2), "r"(a3), "r"(b0), "r"(b1));
}

__device__ __forceinline__ void cp_async16(uint32_t saddr, const void* g) {
    asm volatile("cp.async.cg.shared.global [%0], [%1], 16;" ::"r"(saddr), "l"(g));
}
__device__ __forceinline__ void cp_commit() {
    asm volatile("cp.async.commit_group;" ::: "memory");
}
template <int N>
__device__ __forceinline__ void cp_wait() {
    asm volatile("cp.async.wait_group %0;" ::"n"(N) : "memory");
}

// Issue async copies for one 128x32 fp16 tile (2 x 16B per thread).
__device__ __forceinline__ void load_tile(const __half* __restrict__ src,
                                          int ld, int k0, uint32_t sbase, int tid) {
#pragma unroll
    for (int p = 0; p < 2; ++p) {
        int i = tid + p * 256;
        int row = i >> 2, q = i & 3;
        cp_async16(sbase + (uint32_t)(row * ROW_WORDS + q * 4) * 4,
                   src + (size_t)row * ld + k0 + q * 8);
    }
}

// ---------------------------------------------------------------------------
// GEMM mainloop: accumulates D tile (128x128) into registers.
// acc[am][an][4]: warp (wm=wid&3 rows 32, wn=wid>>2 cols 64), 2 m x 8 n atoms.
// ---------------------------------------------------------------------------
__device__ __forceinline__ void gemm_mainloop(
    const __half* __restrict__ A, int ldA,
    const __half* __restrict__ Bm, int ldB,
    int kTotal, uint32_t* smem, float acc[2][8][4]) {
    const int tid = threadIdx.x;
    const int wid = tid >> 5, lane = tid & 31;
    const int wm = wid & 3, wn = wid >> 2;
    const int lr = lane >> 2, lc = lane & 3;
    const uint32_t sbase = (uint32_t)__cvta_generic_to_shared(smem);
    const int nch = kTotal / 32;

    load_tile(A,  ldA, 0, sbase + 0 * TILE_WORDS * 4, tid);
    load_tile(Bm, ldB, 0, sbase + 1 * TILE_WORDS * 4, tid);
    cp_commit();

    for (int kc = 0; kc < nch; ++kc) {
        if (kc + 1 < nch) {
            uint32_t st = sbase + (uint32_t)(((kc + 1) & 1) * STAGE_WORDS) * 4;
            int k0 = (kc + 1) * 32;
            load_tile(A,  ldA, k0, st + 0 * TILE_WORDS * 4, tid);
            load_tile(Bm, ldB, k0, st + 1 * TILE_WORDS * 4, tid);
            cp_commit();
            cp_wait<1>();
        } else {
            cp_wait<0>();
        }
        __syncthreads();

        const uint32_t* sA = smem + (kc & 1) * STAGE_WORDS;
        const uint32_t* sB = sA + TILE_WORDS;

#pragma unroll
        for (int ks = 0; ks < 2; ++ks) {
            const int w = ks * 8 + lc;
            uint32_t a[2][4];
#pragma unroll
            for (int am = 0; am < 2; ++am) {
                const int r = wm * 32 + am * 16 + lr;
                a[am][0] = sA[r * ROW_WORDS + w];
                a[am][1] = sA[(r + 8) * ROW_WORDS + w];
                a[am][2] = sA[r * ROW_WORDS + w + 4];
                a[am][3] = sA[(r + 8) * ROW_WORDS + w + 4];
            }
#pragma unroll
            for (int an = 0; an < 8; ++an) {
                const int n = wn * 64 + an * 8 + lr;
                uint32_t b0 = sB[n * ROW_WORDS + w];
                uint32_t b1 = sB[n * ROW_WORDS + w + 4];
#pragma unroll
                for (int am = 0; am < 2; ++am)
                    mma16816(acc[am][an], a[am][0], a[am][1], a[am][2], a[am][3], b0, b1);
            }
        }
        __syncthreads();
    }
}

#define EPI_COORDS()                                   \
    const int wid = threadIdx.x >> 5;                  \
    const int lane = threadIdx.x & 31;                 \
    const int wm = wid & 3, wn = wid >> 2;             \
    const int lr = lane >> 2, lc = lane & 3;

// ---------------------------------------------------------------------------
// GEMM kernels
// ---------------------------------------------------------------------------

// q[b,t,o] = featT @ Wq^T + bq -> fp16
__global__ __launch_bounds__(256) void gemm_q_kernel(const float* __restrict__ bq) {
    extern __shared__ uint32_t smem[];
    const int b = blockIdx.z, t0 = blockIdx.x * 128, o0 = blockIdx.y * 128;
    float acc[2][8][4] = {};
    gemm_mainloop(g_featT + ((size_t)b * T + t0) * C, C,
                  g_Wq + (size_t)o0 * C, C, C, smem, acc);
    EPI_COORDS();
#pragma unroll
    for (int am = 0; am < 2; ++am) {
        const int t = t0 + wm * 32 + am * 16 + lr;
#pragma unroll
        for (int an = 0; an < 8; ++an) {
            const int o = o0 + wn * 64 + an * 8 + lc * 2;
            const float b0 = bq[o], b1 = bq[o + 1];
#pragma unroll
            for (int rr = 0; rr < 2; ++rr) {
                const size_t idx = ((size_t)b * T + t + rr * 8) * C + o;
                *reinterpret_cast<__half2*>(&g_q[idx]) = __floats2half2_rn(
                    acc[am][an][rr * 2] + b0, acc[am][an][rr * 2 + 1] + b1);
            }
        }
    }
}

// vT[b,o,t] = Wv @ featT^T + bv -> fp16 (t-contiguous)
__global__ __launch_bounds__(256) void gemm_vt_kernel(const float* __restrict__ bv) {
    extern __shared__ uint32_t smem[];
    const int b = blockIdx.z, t0 = blockIdx.x * 128, o0 = blockIdx.y * 128;
    float acc[2][8][4] = {};
    gemm_mainloop(g_Wv + (size_t)o0 * C, C,
                  g_featT + ((size_t)b * T + t0) * C, C, C, smem, acc);
    EPI_COORDS();
#pragma unroll
    for (int am = 0; am < 2; ++am) {
        const int o = o0 + wm * 32 + am * 16 + lr;
#pragma unroll
        for (int an = 0; an < 8; ++an) {
            const int t = t0 + wn * 64 + an * 8 + lc * 2;
#pragma unroll
            for (int rr = 0; rr < 2; ++rr) {
                const int oo = o + rr * 8;
                const float bo = bv[oo];
                const size_t idx = ((size_t)b * C + oo) * T + t;
                *reinterpret_cast<__half2*>(&g_vT[idx]) = __floats2half2_rn(
                    acc[am][an][rr * 2] + bo, acc[am][an][rr * 2 + 1] + bo);
            }
        }
    }
}

// logits f[b,t,s] = (q @ kT^T) * inv_sqrt_c -> fp16
__global__ __launch_bounds__(256) void gemm_qk_kernel() {
    extern __shared__ uint32_t smem[];
    const int b = blockIdx.z, s0 = blockIdx.x * 128, t0 = blockIdx.y * 128;
    float acc[2][8][4] = {};
    gemm_mainloop(g_q + ((size_t)b * T + t0) * C, C,
                  g_kT + ((size_t)b * T + s0) * C, C, C, smem, acc);
    EPI_COORDS();
#pragma unroll
    for (int am = 0; am < 2; ++am) {
        const int t = t0 + wm * 32 + am * 16 + lr;
#pragma unroll
        for (int an = 0; an < 8; ++an) {
            const int s = s0 + wn * 64 + an * 8 + lc * 2;
#pragma unroll
            for (int rr = 0; rr < 2; ++rr) {
                *reinterpret_cast<__half2*>(&g_fh[((size_t)b * T + t + rr * 8) * T + s]) =
                    __floats2half2_rn(acc[am][an][rr * 2] * INV_SQRT_C,
                                      acc[am][an][rr * 2 + 1] * INV_SQRT_C);
            }
        }
    }
}

// y[b,t,c] = f @ vT^T -> fp16
__global__ __launch_bounds__(256) void gemm_av_kernel() {
    extern __shared__ uint32_t smem[];
    const int b = blockIdx.z, c0 = blockIdx.x * 128, t0 = blockIdx.y * 128;
    float acc[2][8][4] = {};
    gemm_mainloop(g_fh + ((size_t)b * T + t0) * T, T,
                  g_vT + ((size_t)b * C + c0) * T, T, T, smem, acc);
    EPI_COORDS();
#pragma unroll
    for (int am = 0; am < 2; ++am) {
        const int t = t0 + wm * 32 + am * 16 + lr;
#pragma unroll
        for (int an = 0; an < 8; ++an) {
            const int c = c0 + wn * 64 + an * 8 + lc * 2;
#pragma unroll
            for (int rr = 0; rr < 2; ++rr) {
                const size_t idx = ((size_t)b * T + t + rr * 8) * C + c;
                *reinterpret_cast<__half2*>(&g_y[idx]) =
                    __floats2half2_rn(acc[am][an][rr * 2], acc[am][an][rr * 2 + 1]);
            }
        }
    }
}

// out[b,o,t] = feat + Ws @ y^T + bs   (fp32, pre-LN)
__global__ __launch_bounds__(256) void gemm_smooth_kernel(const float* __restrict__ bs,
                                                          const float* __restrict__ feat,
                                                          float* __restrict__ out) {
    extern __shared__ uint32_t smem[];
    const int b = blockIdx.z, t0 = blockIdx.x * 128, o0 = blockIdx.y * 128;
    float acc[2][8][4] = {};
    gemm_mainloop(g_Ws + (size_t)o0 * C, C,
                  g_y + ((size_t)b * T + t0) * C, C, C, smem, acc);
    EPI_COORDS();
#pragma unroll
    for (int am = 0; am < 2; ++am) {
        const int o = o0 + wm * 32 + am * 16 + lr;
#pragma unroll
        for (int an = 0; an < 8; ++an) {
            const int t = t0 + wn * 64 + an * 8 + lc * 2;
#pragma unroll
            for (int rr = 0; rr < 2; ++rr) {
                const int oo = o + rr * 8;
                const float bo = bs[oo];
                const size_t idx = ((size_t)b * C + oo) * T + t;
                float2 fv = *reinterpret_cast<const float2*>(&feat[idx]);
                float2 v;
                v.x = fv.x + acc[am][an][rr * 2] + bo;
                v.y = fv.y + acc[am][an][rr * 2 + 1] + bo;
                *reinterpret_cast<float2*>(&out[idx]) = v;
            }
        }
    }
}

// ---------------------------------------------------------------------------
// Elementwise / reduction kernels
// ---------------------------------------------------------------------------
__global__ void zero_kernel() {
    int i = threadIdx.x;
    if (i < B) { g_lnsum[i] = 0.0; g_lnsq[i] = 0.0; }
}

__global__ void wksum_kernel(const float* __restrict__ Wk) {
    int c = blockIdx.x * 256 + threadIdx.x;
    if (c >= C) return;
    float s = 0.0f;
    for (int o = 0; o < C; ++o) s += Wk[(size_t)o * C + c];
    g_wksum[c] = s;
}

// feat [B,C,T] -> featT fp16 [B,T,C]; kT fp16 = wksum*feat + bk
__global__ void transpose_kernel(const float* __restrict__ feat,
                                 const float* __restrict__ bk) {
    __shared__ float tile[32][33];
    const int b = blockIdx.z;
    const int t0 = blockIdx.x * 32, c0 = blockIdx.y * 32;
    const int tx = threadIdx.x, ty = threadIdx.y;
#pragma unroll
    for (int i = 0; i < 4; ++i)
        tile[ty + 8 * i][tx] = feat[((size_t)b * C + c0 + ty + 8 * i) * T + t0 + tx];
    __syncthreads();
    const int c = c0 + tx;
    const float wk = g_wksum[c], bkc = bk[c];
#pragma unroll
    for (int i = 0; i < 4; ++i) {
        const int t = t0 + ty + 8 * i;
        const float v = tile[tx][ty + 8 * i];
        const size_t idx = ((size_t)b * T + t) * C + c;
        g_featT[idx] = __float2half_rn(v);
        g_kT[idx]    = __float2half_rn(wk * v + bkc);
    }
}

__global__ void convertw_kernel(const float* __restrict__ Wq,
                                const float* __restrict__ Wv,
                                const float* __restrict__ Ws) {
    int i = blockIdx.x * 256 + threadIdx.x;
    if (i >= C * C) return;
    g_Wq[i] = __float2half_rn(Wq[i]);
    g_Wv[i] = __float2half_rn(Wv[i]);
    g_Ws[i] = __float2half_rn(Ws[i]);
}

// Row softmax over s (fp16 logits in, fp16 probs out, in place)
__global__ void softmax_kernel() {
    __shared__ float buf[T];
    __shared__ float red[256];
    const size_t base = (size_t)blockIdx.x * T;  // b*T + t
    const int tid = threadIdx.x;
    float m = -1e30f;
    for (int s = tid; s < T; s += 256) {
        float x = __half2float(g_fh[base + s]);
        buf[s] = x;
        m = fmaxf(m, x);
    }
    red[tid] = m;
    __syncthreads();
    for (int off = 128; off > 0; off >>= 1) {
        if (tid < off) red[tid] = fmaxf(red[tid], red[tid + off]);
        __syncthreads();
    }
    m = red[0];
    __syncthreads();
    float sum = 0.0f;
    for (int s = tid; s < T; s += 256) {
        float e = __expf(buf[s] - m);
        buf[s] = e;
        sum += e;
    }
    red[tid] = sum;
    __syncthreads();
    for (int off = 128; off > 0; off >>= 1) {
        if (tid < off) red[tid] += red[tid + off];
        __syncthreads();
    }
    const float inv = 1.0f / red[0];
    for (int s = tid * 2; s < T; s += 512)
        *reinterpret_cast<__half2*>(&g_fh[base + s]) =
            __floats2half2_rn(buf[s] * inv, buf[s + 1] * inv);
}

__global__ void vsum_kernel() {
    __shared__ float red[256];
    const int c = blockIdx.x, b = blockIdx.y, tid = threadIdx.x;
    const __half* p = g_vT + ((size_t)b * C + c) * T;
    float s = 0.0f;
    for (int t = tid; t < T; t += 256) s += __half2float(p[t]);
    red[tid] = s;
    __syncthreads();
    for (int off = 128; off > 0; off >>= 1) {
        if (tid < off) red[tid] += red[tid + off];
        __syncthreads();
    }
    if (tid == 0) g_vsum[b * C + c] = red[0];
}

__global__ void vsumwl_kernel(const float* __restrict__ Wl) {
    __shared__ float red[128];
    const int b = blockIdx.x, tid = threadIdx.x;
    float s = 0.0f;
    for (int c = tid; c < C; c += 128) s += g_vsum[b * C + c] * Wl[c];
    red[tid] = s;
    __syncthreads();
    for (int off = 64; off > 0; off >>= 1) {
        if (tid < off) red[tid] += red[tid + off];
        __syncthreads();
    }
    if (tid == 0) g_vsumWl[b] = red[0];
}

__global__ void score_kernel(const float* __restrict__ Wl,
                             const float* __restrict__ bl,
                             float* __restrict__ score) {
    __shared__ float red[128];
    const int row = blockIdx.x;  // b*T + t
    const int b = row / T;
    const int tid = threadIdx.x;
    const __half* yr = g_y + (size_t)row * C;
    float s = 0.0f;
    for (int c = tid; c < C; c += 128) s += __half2float(yr[c]) * Wl[c];
    red[tid] = s;
    __syncthreads();
    for (int off = 64; off > 0; off >>= 1) {
        if (tid < off) red[tid] += red[tid + off];
        __syncthreads();
    }
    if (tid == 0) {
        float yl = red[0];
        float zl = g_vsumWl[b] - yl;
        float b0 = bl[0];
        float fs = 1.0f / (1.0f + expf(-(yl + b0)));
        float bsc = 1.0f - 1.0f / (1.0f + expf(-(zl + b0)));
        score[row] = 0.5f * (fs + bsc);
    }
}

__global__ void ln1_kernel(const float* __restrict__ out) {
    __shared__ double rs[256];
    __shared__ double rq[256];
    const int b = blockIdx.y;
    const float* p = out + (size_t)b * C * T;
    const int n = C * T;
    const int tid = threadIdx.x;
    double ls = 0.0, lq = 0.0;
    for (int i = blockIdx.x * 256 + tid; i < n; i += gridDim.x * 256) {
        float x = p[i];
        ls += (double)x;
        lq += (double)x * (double)x;
    }
    rs[tid] = ls; rq[tid] = lq;
    __syncthreads();
    for (int off = 128; off > 0; off >>= 1) {
        if (tid < off) { rs[tid] += rs[tid + off]; rq[tid] += rq[tid + off]; }
        __syncthreads();
    }
    if (tid == 0) {
        atomicAdd(&g_lnsum[b], rs[0]);
        atomicAdd(&g_lnsq[b], rq[0]);
    }
}

__global__ void ln2_kernel(float* __restrict__ out) {
    const int b = blockIdx.y;
    const int i = blockIdx.x * 256 + threadIdx.x;
    const double n = (double)(C * T);
    double mu = g_lnsum[b] / n;
    double var = g_lnsq[b] / n - mu * mu;
    float muf = (float)mu;
    float inv = rsqrtf((float)var + LN_EPS);
    size_t oi = (size_t)b * C * T + i;
    out[oi] = (out[oi] - muf) * inv;
}

}  // namespace

// ---------------------------------------------------------------------------
extern "C" void kernel_launch(void* const* d_in, const int* in_sizes, int n_in,
                              void* d_out, int out_size) {
    const float* feat = (const float*)d_in[0];
    const float* Wq   = (const float*)d_in[1];
    const float* bq   = (const float*)d_in[2];
    const float* Wk   = (const float*)d_in[3];
    const float* bk   = (const float*)d_in[4];
    const float* Wv   = (const float*)d_in[5];
    const float* bv   = (const float*)d_in[6];
    const float* Ws   = (const float*)d_in[7];
    const float* bs   = (const float*)d_in[8];
    const float* Wl   = (const float*)d_in[9];
    const float* bl   = (const float*)d_in[10];
    float* out = (float*)d_out;
    float* score = out + (size_t)B * C * T;

    cudaFuncSetAttribute(gemm_q_kernel,      cudaFuncAttributeMaxDynamicSharedMemorySize, SMEM_BYTES);
    cudaFuncSetAttribute(gemm_vt_kernel,     cudaFuncAttributeMaxDynamicSharedMemorySize, SMEM_BYTES);
    cudaFuncSetAttribute(gemm_qk_kernel,     cudaFuncAttributeMaxDynamicSharedMemorySize, SMEM_BYTES);
    cudaFuncSetAttribute(gemm_av_kernel,     cudaFuncAttributeMaxDynamicSharedMemorySize, SMEM_BYTES);
    cudaFuncSetAttribute(gemm_smooth_kernel, cudaFuncAttributeMaxDynamicSharedMemorySize, SMEM_BYTES);

    zero_kernel<<<1, 32>>>();
    wksum_kernel<<<2, 256>>>(Wk);
    transpose_kernel<<<dim3(T / 32, C / 32, B), dim3(32, 8)>>>(feat, bk);
    convertw_kernel<<<(C * C + 255) / 256, 256>>>(Wq, Wv, Ws);

    gemm_q_kernel<<<dim3(T / 128, C / 128, B), 256, SMEM_BYTES>>>(bq);
    gemm_vt_kernel<<<dim3(T / 128, C / 128, B), 256, SMEM_BYTES>>>(bv);
    gemm_qk_kernel<<<dim3(T / 128, T / 128, B), 256, SMEM_BYTES>>>();
    softmax_kernel<<<B * T, 256>>>();
    gemm_av_kernel<<<dim3(C / 128, T / 128, B), 256, SMEM_BYTES>>>();

    vsum_kernel<<<dim3(C, B), 256>>>();
    vsumwl_kernel<<<B, 128>>>(Wl);
    score_kernel<<<B * T, 128>>>(Wl, bl, score);

    gemm_smooth_kernel<<<dim3(T / 128, C / 128, B), 256, SMEM_BYTES>>>(bs, feat, out);

    ln1_kernel<<<dim3(64, B), 256>>>(out);
    ln2_kernel<<<dim3((C * T) / 256, B), 256>>>(out);
}

// round 5
// speedup vs baseline: 6.8563x; 1.8660x over previous
#include <cuda_runtime.h>
#include <cuda_fp16.h>
#include <math.h>
#include <stdint.h>

// ---------------------------------------------------------------------------
// ForegroundAttentionModule, B=4, C=512, T=2048, fp32 in/out.
// fp16 mma.sync GEMMs (f32 accum), single product (validated rel_err ~4e-5).
// Algebra: key_ einsum collapses; q.k row-constant (q.bk) cancels in softmax
//   -> kT eliminated, wksum folded into q epilogue. z = colsum(v) - y.
// GEMM: D[M,N] = sum_K A[M,K]*B[N,K]. CTA 128x128, K chunk 32, 4-stage
// cp.async pipeline, ldmatrix fragments, 8 warps (4M x 2N), warp 32x64.
// ---------------------------------------------------------------------------

namespace {

constexpr int B = 4;
constexpr int C = 512;
constexpr int T = 2048;
constexpr float LN_EPS = 1e-5f;
constexpr float INV_SQRT_C = 0.04419417382415922f;

constexpr int ROW_BYTES   = 80;                  // 32 fp16 + 16B pad
constexpr int TILE_BYTES  = 128 * ROW_BYTES;     // 10240
constexpr int STAGE_BYTES = 2 * TILE_BYTES;      // A + B
constexpr int NSTAGES     = 4;
constexpr int SMEM_BYTES  = NSTAGES * STAGE_BYTES;  // 81920

// ---------------- device scratch -------------------------------------------
__device__ __half g_featT[(size_t)B * T * C];   // [B,T,C]
__device__ __half g_q[(size_t)B * T * C];       // [B,T,C] (pre-scaled by wksum)
__device__ __half g_vT[(size_t)B * C * T];      // [B,C,T]
__device__ __half g_y[(size_t)B * T * C];       // [B,T,C]
__device__ __half g_fh[(size_t)B * T * T];      // [B,T,T] logits -> probs
__device__ __half g_Wq[C * C], g_Wv[C * C], g_Ws[C * C];
__device__ float  g_wksum[C];
__device__ float  g_vsum[B * C];
__device__ float  g_vsumWl[B];
__device__ double g_lnsum[B], g_lnsq[B];

// ---------------- helpers ---------------------------------------------------
__device__ __forceinline__ void mma16816(float* c, uint32_t a0, uint32_t a1,
                                         uint32_t a2, uint32_t a3,
                                         uint32_t b0, uint32_t b1) {
    asm volatile(
        "mma.sync.aligned.m16n8k16.row.col.f32.f16.f16.f32 "
        "{%0,%1,%2,%3}, {%4,%5,%6,%7}, {%8,%9}, {%0,%1,%2,%3};"
        : "+f"(c[0]), "+f"(c[1]), "+f"(c[2]), "+f"(c[3])
        : "r"(a0), "r"(a1), "r"(a2), "r"(a3), "r"(b0), "r"(b1));
}

__device__ __forceinline__ void ldsm_x4(uint32_t& r0, uint32_t& r1,
                                        uint32_t& r2, uint32_t& r3, uint32_t addr) {
    asm volatile("ldmatrix.sync.aligned.m8n8.x4.shared.b16 {%0,%1,%2,%3}, [%4];"
                 : "=r"(r0), "=r"(r1), "=r"(r2), "=r"(r3) : "r"(addr));
}
__device__ __forceinline__ void ldsm_x2(uint32_t& r0, uint32_t& r1, uint32_t addr) {
    asm volatile("ldmatrix.sync.aligned.m8n8.x2.shared.b16 {%0,%1}, [%2];"
                 : "=r"(r0), "=r"(r1) : "r"(addr));
}

__device__ __forceinline__ void cp_async16(uint32_t saddr, const void* g) {
    asm volatile("cp.async.cg.shared.global [%0], [%1], 16;" ::"r"(saddr), "l"(g));
}
__device__ __forceinline__ void cp_commit() {
    asm volatile("cp.async.commit_group;" ::: "memory");
}
template <int N>
__device__ __forceinline__ void cp_wait() {
    asm volatile("cp.async.wait_group %0;" ::"n"(N) : "memory");
}

// One 128x32 fp16 tile -> smem stage (2 x 16B per thread).
__device__ __forceinline__ void load_tile(const __half* __restrict__ src,
                                          int ld, int k0, uint32_t sbase, int tid) {
#pragma unroll
    for (int p = 0; p < 2; ++p) {
        int i = tid + p * 256;
        int row = i >> 2, q = i & 3;
        cp_async16(sbase + (uint32_t)(row * ROW_BYTES + q * 16),
                   src + (size_t)row * ld + k0 + q * 8);
    }
}

// ---------------------------------------------------------------------------
// GEMM mainloop: 4-stage pipeline, ldmatrix fragments.
// ---------------------------------------------------------------------------
__device__ __forceinline__ void gemm_mainloop(
    const __half* __restrict__ A, int ldA,
    const __half* __restrict__ Bm, int ldB,
    int kTotal, char* smem, float acc[2][8][4]) {
    const int tid = threadIdx.x;
    const int wid = tid >> 5, lane = tid & 31;
    const int wm = wid & 3, wn = wid >> 2;
    const uint32_t sbase = (uint32_t)__cvta_generic_to_shared(smem);
    const int nch = kTotal / 32;

    // per-lane ldmatrix base offsets (within a stage)
    const uint32_t aOff = (uint32_t)((wm * 32 + (lane & 15)) * ROW_BYTES + (lane >> 4) * 16);
    const uint32_t bOff = (uint32_t)(TILE_BYTES +
                          (wn * 64 + (lane & 7)) * ROW_BYTES + ((lane >> 3) & 1) * 16);

#pragma unroll
    for (int s = 0; s < 3; ++s) {
        load_tile(A,  ldA, s * 32, sbase + s * STAGE_BYTES, tid);
        load_tile(Bm, ldB, s * 32, sbase + s * STAGE_BYTES + TILE_BYTES, tid);
        cp_commit();
    }

    for (int kc = 0; kc < nch; ++kc) {
        cp_wait<2>();
        __syncthreads();
        if (kc + 3 < nch) {
            uint32_t st = sbase + (uint32_t)(((kc + 3) & 3) * STAGE_BYTES);
            load_tile(A,  ldA, (kc + 3) * 32, st, tid);
            load_tile(Bm, ldB, (kc + 3) * 32, st + TILE_BYTES, tid);
        }
        cp_commit();

        const uint32_t sg = sbase + (uint32_t)((kc & 3) * STAGE_BYTES);
#pragma unroll
        for (int ks = 0; ks < 2; ++ks) {
            uint32_t a[2][4];
            ldsm_x4(a[0][0], a[0][1], a[0][2], a[0][3], sg + aOff + ks * 32);
            ldsm_x4(a[1][0], a[1][1], a[1][2], a[1][3], sg + aOff + 16 * ROW_BYTES + ks * 32);
#pragma unroll
            for (int an = 0; an < 8; ++an) {
                uint32_t b0, b1;
                ldsm_x2(b0, b1, sg + bOff + an * 8 * ROW_BYTES + ks * 32);
                mma16816(acc[0][an], a[0][0], a[0][1], a[0][2], a[0][3], b0, b1);
                mma16816(acc[1][an], a[1][0], a[1][1], a[1][2], a[1][3], b0, b1);
            }
        }
    }
}

#define EPI_COORDS()                                   \
    const int wid = threadIdx.x >> 5;                  \
    const int lane = threadIdx.x & 31;                 \
    const int wm = wid & 3, wn = wid >> 2;             \
    const int lr = lane >> 2, lc = lane & 3;

// ---------------------------------------------------------------------------
// GEMM kernels
// ---------------------------------------------------------------------------

// q'[b,t,o] = (featT @ Wq^T + bq) * wksum[o] -> fp16
__global__ __launch_bounds__(256, 2) void gemm_q_kernel(const float* __restrict__ bq) {
    extern __shared__ char smem[];
    const int b = blockIdx.z, t0 = blockIdx.x * 128, o0 = blockIdx.y * 128;
    float acc[2][8][4] = {};
    gemm_mainloop(g_featT + ((size_t)b * T + t0) * C, C,
                  g_Wq + (size_t)o0 * C, C, C, smem, acc);
    EPI_COORDS();
#pragma unroll
    for (int am = 0; am < 2; ++am) {
        const int t = t0 + wm * 32 + am * 16 + lr;
#pragma unroll
        for (int an = 0; an < 8; ++an) {
            const int o = o0 + wn * 64 + an * 8 + lc * 2;
            const float b0 = bq[o], b1 = bq[o + 1];
            const float w0 = g_wksum[o], w1 = g_wksum[o + 1];
#pragma unroll
            for (int rr = 0; rr < 2; ++rr) {
                const size_t idx = ((size_t)b * T + t + rr * 8) * C + o;
                *reinterpret_cast<__half2*>(&g_q[idx]) = __floats2half2_rn(
                    (acc[am][an][rr * 2] + b0) * w0,
                    (acc[am][an][rr * 2 + 1] + b1) * w1);
            }
        }
    }
}

// vT[b,o,t] = Wv @ featT^T + bv -> fp16
__global__ __launch_bounds__(256, 2) void gemm_vt_kernel(const float* __restrict__ bv) {
    extern __shared__ char smem[];
    const int b = blockIdx.z, t0 = blockIdx.x * 128, o0 = blockIdx.y * 128;
    float acc[2][8][4] = {};
    gemm_mainloop(g_Wv + (size_t)o0 * C, C,
                  g_featT + ((size_t)b * T + t0) * C, C, C, smem, acc);
    EPI_COORDS();
#pragma unroll
    for (int am = 0; am < 2; ++am) {
        const int o = o0 + wm * 32 + am * 16 + lr;
#pragma unroll
        for (int an = 0; an < 8; ++an) {
            const int t = t0 + wn * 64 + an * 8 + lc * 2;
#pragma unroll
            for (int rr = 0; rr < 2; ++rr) {
                const int oo = o + rr * 8;
                const float bo = bv[oo];
                const size_t idx = ((size_t)b * C + oo) * T + t;
                *reinterpret_cast<__half2*>(&g_vT[idx]) = __floats2half2_rn(
                    acc[am][an][rr * 2] + bo, acc[am][an][rr * 2 + 1] + bo);
            }
        }
    }
}

// logits f[b,t,s] = (q' @ featT^T) * inv_sqrt_c -> fp16 (row const dropped)
__global__ __launch_bounds__(256, 2) void gemm_qk_kernel() {
    extern __shared__ char smem[];
    const int b = blockIdx.z, s0 = blockIdx.x * 128, t0 = blockIdx.y * 128;
    float acc[2][8][4] = {};
    gemm_mainloop(g_q + ((size_t)b * T + t0) * C, C,
                  g_featT + ((size_t)b * T + s0) * C, C, C, smem, acc);
    EPI_COORDS();
#pragma unroll
    for (int am = 0; am < 2; ++am) {
        const int t = t0 + wm * 32 + am * 16 + lr;
#pragma unroll
        for (int an = 0; an < 8; ++an) {
            const int s = s0 + wn * 64 + an * 8 + lc * 2;
#pragma unroll
            for (int rr = 0; rr < 2; ++rr) {
                *reinterpret_cast<__half2*>(&g_fh[((size_t)b * T + t + rr * 8) * T + s]) =
                    __floats2half2_rn(acc[am][an][rr * 2] * INV_SQRT_C,
                                      acc[am][an][rr * 2 + 1] * INV_SQRT_C);
            }
        }
    }
}

// y[b,t,c] = f @ vT^T -> fp16
__global__ __launch_bounds__(256, 2) void gemm_av_kernel() {
    extern __shared__ char smem[];
    const int b = blockIdx.z, c0 = blockIdx.x * 128, t0 = blockIdx.y * 128;
    float acc[2][8][4] = {};
    gemm_mainloop(g_fh + ((size_t)b * T + t0) * T, T,
                  g_vT + ((size_t)b * C + c0) * T, T, T, smem, acc);
    EPI_COORDS();
#pragma unroll
    for (int am = 0; am < 2; ++am) {
        const int t = t0 + wm * 32 + am * 16 + lr;
#pragma unroll
        for (int an = 0; an < 8; ++an) {
            const int c = c0 + wn * 64 + an * 8 + lc * 2;
#pragma unroll
            for (int rr = 0; rr < 2; ++rr) {
                const size_t idx = ((size_t)b * T + t + rr * 8) * C + c;
                *reinterpret_cast<__half2*>(&g_y[idx]) =
                    __floats2half2_rn(acc[am][an][rr * 2], acc[am][an][rr * 2 + 1]);
            }
        }
    }
}

// out[b,o,t] = feat + Ws @ y^T + bs; fused LN pass-1 partials.
__global__ __launch_bounds__(256, 2) void gemm_smooth_kernel(const float* __restrict__ bs,
                                                             const float* __restrict__ feat,
                                                             float* __restrict__ out) {
    extern __shared__ char smem[];
    const int b = blockIdx.z, t0 = blockIdx.x * 128, o0 = blockIdx.y * 128;
    float acc[2][8][4] = {};
    gemm_mainloop(g_Ws + (size_t)o0 * C, C,
                  g_y + ((size_t)b * T + t0) * C, C, C, smem, acc);
    EPI_COORDS();
    float psum = 0.0f, psq = 0.0f;
#pragma unroll
    for (int am = 0; am < 2; ++am) {
        const int o = o0 + wm * 32 + am * 16 + lr;
#pragma unroll
        for (int an = 0; an < 8; ++an) {
            const int t = t0 + wn * 64 + an * 8 + lc * 2;
#pragma unroll
            for (int rr = 0; rr < 2; ++rr) {
                const int oo = o + rr * 8;
                const float bo = bs[oo];
                const size_t idx = ((size_t)b * C + oo) * T + t;
                float2 fv = *reinterpret_cast<const float2*>(&feat[idx]);
                float2 v;
                v.x = fv.x + acc[am][an][rr * 2] + bo;
                v.y = fv.y + acc[am][an][rr * 2 + 1] + bo;
                *reinterpret_cast<float2*>(&out[idx]) = v;
                psum += v.x + v.y;
                psq  += v.x * v.x + v.y * v.y;
            }
        }
    }
    // block-reduce LN partials, one double atomic per block
    __syncthreads();  // mainloop smem no longer needed
    float* red = reinterpret_cast<float*>(smem);
#pragma unroll
    for (int off = 16; off > 0; off >>= 1) {
        psum += __shfl_xor_sync(0xFFFFFFFFu, psum, off);
        psq  += __shfl_xor_sync(0xFFFFFFFFu, psq,  off);
    }
    if (lane == 0) { red[wid] = psum; red[8 + wid] = psq; }
    __syncthreads();
    if (threadIdx.x == 0) {
        float s = 0.0f, q = 0.0f;
#pragma unroll
        for (int w = 0; w < 8; ++w) { s += red[w]; q += red[8 + w]; }
        atomicAdd(&g_lnsum[b], (double)s);
        atomicAdd(&g_lnsq[b],  (double)q);
    }
}

// ---------------------------------------------------------------------------
// Elementwise / reduction kernels
// ---------------------------------------------------------------------------
__global__ void wksum_kernel(const float* __restrict__ Wk) {
    int c = blockIdx.x * 256 + threadIdx.x;
    if (c < B && blockIdx.x == 0) { g_lnsum[c] = 0.0; g_lnsq[c] = 0.0; }
    if (c >= C) return;
    float s = 0.0f;
    for (int o = 0; o < C; ++o) s += Wk[(size_t)o * C + c];
    g_wksum[c] = s;
}

// feat [B,C,T] -> featT fp16 [B,T,C]
__global__ void transpose_kernel(const float* __restrict__ feat) {
    __shared__ float tile[32][33];
    const int b = blockIdx.z;
    const int t0 = blockIdx.x * 32, c0 = blockIdx.y * 32;
    const int tx = threadIdx.x, ty = threadIdx.y;
#pragma unroll
    for (int i = 0; i < 4; ++i)
        tile[ty + 8 * i][tx] = feat[((size_t)b * C + c0 + ty + 8 * i) * T + t0 + tx];
    __syncthreads();
    const int c = c0 + tx;
#pragma unroll
    for (int i = 0; i < 4; ++i) {
        const int t = t0 + ty + 8 * i;
        g_featT[((size_t)b * T + t) * C + c] = __float2half_rn(tile[tx][ty + 8 * i]);
    }
}

__global__ void convertw_kernel(const float* __restrict__ Wq,
                                const float* __restrict__ Wv,
                                const float* __restrict__ Ws) {
    int i = blockIdx.x * 256 + threadIdx.x;
    if (i >= C * C) return;
    g_Wq[i] = __float2half_rn(Wq[i]);
    g_Wv[i] = __float2half_rn(Wv[i]);
    g_Ws[i] = __float2half_rn(Ws[i]);
}

// Row softmax over s (fp16 in/out, in place)
__global__ void softmax_kernel() {
    __shared__ float buf[T];
    __shared__ float red[256];
    const size_t base = (size_t)blockIdx.x * T;  // b*T + t
    const int tid = threadIdx.x;
    float m = -1e30f;
    for (int s = tid; s < T; s += 256) {
        float x = __half2float(g_fh[base + s]);
        buf[s] = x;
        m = fmaxf(m, x);
    }
    red[tid] = m;
    __syncthreads();
    for (int off = 128; off > 0; off >>= 1) {
        if (tid < off) red[tid] = fmaxf(red[tid], red[tid + off]);
        __syncthreads();
    }
    m = red[0];
    __syncthreads();
    float sum = 0.0f;
    for (int s = tid; s < T; s += 256) {
        float e = __expf(buf[s] - m);
        buf[s] = e;
        sum += e;
    }
    red[tid] = sum;
    __syncthreads();
    for (int off = 128; off > 0; off >>= 1) {
        if (tid < off) red[tid] += red[tid + off];
        __syncthreads();
    }
    const float inv = 1.0f / red[0];
    for (int s = tid * 2; s < T; s += 512)
        *reinterpret_cast<__half2*>(&g_fh[base + s]) =
            __floats2half2_rn(buf[s] * inv, buf[s + 1] * inv);
}

__global__ void vsum_kernel() {
    __shared__ float red[256];
    const int c = blockIdx.x, b = blockIdx.y, tid = threadIdx.x;
    const __half* p = g_vT + ((size_t)b * C + c) * T;
    float s = 0.0f;
    for (int t = tid; t < T; t += 256) s += __half2float(p[t]);
    red[tid] = s;
    __syncthreads();
    for (int off = 128; off > 0; off >>= 1) {
        if (tid < off) red[tid] += red[tid + off];
        __syncthreads();
    }
    if (tid == 0) g_vsum[b * C + c] = red[0];
}

__global__ void vsumwl_kernel(const float* __restrict__ Wl) {
    __shared__ float red[128];
    const int b = blockIdx.x, tid = threadIdx.x;
    float s = 0.0f;
    for (int c = tid; c < C; c += 128) s += g_vsum[b * C + c] * Wl[c];
    red[tid] = s;
    __syncthreads();
    for (int off = 64; off > 0; off >>= 1) {
        if (tid < off) red[tid] += red[tid + off];
        __syncthreads();
    }
    if (tid == 0) g_vsumWl[b] = red[0];
}

__global__ void score_kernel(const float* __restrict__ Wl,
                             const float* __restrict__ bl,
                             float* __restrict__ score) {
    __shared__ float red[128];
    const int row = blockIdx.x;  // b*T + t
    const int b = row / T;
    const int tid = threadIdx.x;
    const __half* yr = g_y + (size_t)row * C;
    float s = 0.0f;
    for (int c = tid; c < C; c += 128) s += __half2float(yr[c]) * Wl[c];
    red[tid] = s;
    __syncthreads();
    for (int off = 64; off > 0; off >>= 1) {
        if (tid < off) red[tid] += red[tid + off];
        __syncthreads();
    }
    if (tid == 0) {
        float yl = red[0];
        float zl = g_vsumWl[b] - yl;
        float b0 = bl[0];
        float fs = 1.0f / (1.0f + expf(-(yl + b0)));
        float bsc = 1.0f - 1.0f / (1.0f + expf(-(zl + b0)));
        score[row] = 0.5f * (fs + bsc);
    }
}

__global__ void ln2_kernel(float* __restrict__ out) {
    const int b = blockIdx.y;
    const int i = blockIdx.x * 256 + threadIdx.x;
    const double n = (double)(C * T);
    double mu = g_lnsum[b] / n;
    double var = g_lnsq[b] / n - mu * mu;
    float muf = (float)mu;
    float inv = rsqrtf((float)var + LN_EPS);
    size_t oi = (size_t)b * C * T + i;
    out[oi] = (out[oi] - muf) * inv;
}

}  // namespace

// ---------------------------------------------------------------------------
extern "C" void kernel_launch(void* const* d_in, const int* in_sizes, int n_in,
                              void* d_out, int out_size) {
    const float* feat = (const float*)d_in[0];
    const float* Wq   = (const float*)d_in[1];
    const float* bq   = (const float*)d_in[2];
    const float* Wk   = (const float*)d_in[3];
    const float* bk   = (const float*)d_in[4];  // unused: cancels in softmax
    const float* Wv   = (const float*)d_in[5];
    const float* bv   = (const float*)d_in[6];
    const float* Ws   = (const float*)d_in[7];
    const float* bs   = (const float*)d_in[8];
    const float* Wl   = (const float*)d_in[9];
    const float* bl   = (const float*)d_in[10];
    float* out = (float*)d_out;
    float* score = out + (size_t)B * C * T;
    (void)bk;

    cudaFuncSetAttribute(gemm_q_kernel,      cudaFuncAttributeMaxDynamicSharedMemorySize, SMEM_BYTES);
    cudaFuncSetAttribute(gemm_vt_kernel,     cudaFuncAttributeMaxDynamicSharedMemorySize, SMEM_BYTES);
    cudaFuncSetAttribute(gemm_qk_kernel,     cudaFuncAttributeMaxDynamicSharedMemorySize, SMEM_BYTES);
    cudaFuncSetAttribute(gemm_av_kernel,     cudaFuncAttributeMaxDynamicSharedMemorySize, SMEM_BYTES);
    cudaFuncSetAttribute(gemm_smooth_kernel, cudaFuncAttributeMaxDynamicSharedMemorySize, SMEM_BYTES);

    wksum_kernel<<<2, 256>>>(Wk);
    transpose_kernel<<<dim3(T / 32, C / 32, B), dim3(32, 8)>>>(feat);
    convertw_kernel<<<(C * C + 255) / 256, 256>>>(Wq, Wv, Ws);

    gemm_q_kernel<<<dim3(T / 128, C / 128, B), 256, SMEM_BYTES>>>(bq);
    gemm_vt_kernel<<<dim3(T / 128, C / 128, B), 256, SMEM_BYTES>>>(bv);
    gemm_qk_kernel<<<dim3(T / 128, T / 128, B), 256, SMEM_BYTES>>>();
    softmax_kernel<<<B * T, 256>>>();
    gemm_av_kernel<<<dim3(C / 128, T / 128, B), 256, SMEM_BYTES>>>();

    vsum_kernel<<<dim3(C, B), 256>>>();
    vsumwl_kernel<<<B, 128>>>(Wl);
    score_kernel<<<B * T, 128>>>(Wl, bl, score);

    gemm_smooth_kernel<<<dim3(T / 128, C / 128, B), 256, SMEM_BYTES>>>(bs, feat, out);

    ln2_kernel<<<dim3((C * T) / 256, B), 256>>>(out);
}